// round 16
// baseline (speedup 1.0000x reference)
#include <cuda_runtime.h>
#include <cuda_fp16.h>
#include <cstdint>

#define D 128
#define K 64
#define TILE 128
#define NT_MAX 1563
#define NB 148
#define TEMP 30.0f
#define EPSn 1e-6f
#define ITERS 11

// smem byte offsets
#define OFF_MU 0                 // MuH 16KB | MuL 16KB (fp16)
#define OFF_X  32768             // buf0: Xh 32K | Xl 32K ; buf1 at +65536
#define OFF_R  163840            // Rh 16K (128 rows x 64 kc x 2B)
#define OFF_CNT 180224           // snorm/sSum (256 f) | scnt (256 f)
#define SMEM_TOTAL (OFF_CNT + 2048)

__device__ __align__(16) unsigned char g_x[(size_t)NT_MAX * 65536]; // per tile: Xh 32K | Xl 32K, swizzled fp16
__device__ float g_mu_raw[(ITERS + 1) * K * D];
__device__ float g_cc[(ITERS + 1) * K];

__device__ __forceinline__ uint32_t smem_u32(const void* p) {
    uint32_t a;
    asm("{ .reg .u64 t; cvta.to.shared.u64 t, %1; cvt.u32.u64 %0, t; }" : "=r"(a) : "l"(p));
    return a;
}
__device__ __forceinline__ void ldsm_x4(uint32_t* r, uint32_t a) {
    asm volatile("ldmatrix.sync.aligned.m8n8.x4.shared.b16 {%0,%1,%2,%3}, [%4];"
        : "=r"(r[0]), "=r"(r[1]), "=r"(r[2]), "=r"(r[3]) : "r"(a));
}
__device__ __forceinline__ void ldsm_x4t(uint32_t* r, uint32_t a) {
    asm volatile("ldmatrix.sync.aligned.m8n8.x4.trans.shared.b16 {%0,%1,%2,%3}, [%4];"
        : "=r"(r[0]), "=r"(r[1]), "=r"(r[2]), "=r"(r[3]) : "r"(a));
}
__device__ __forceinline__ void mma_f16(float* c, const uint32_t* a, const uint32_t* b) {
    asm volatile("mma.sync.aligned.m16n8k16.row.col.f32.f16.f16.f32 "
        "{%0,%1,%2,%3}, {%4,%5,%6,%7}, {%8,%9}, {%0,%1,%2,%3};"
        : "+f"(c[0]), "+f"(c[1]), "+f"(c[2]), "+f"(c[3])
        : "r"(a[0]), "r"(a[1]), "r"(a[2]), "r"(a[3]), "r"(b[0]), "r"(b[1]));
}
__device__ __forceinline__ void cp16(uint32_t dst, const void* src) {
    asm volatile("cp.async.cg.shared.global [%0], [%1], 16;" :: "r"(dst), "l"(src) : "memory");
}
#define CP_COMMIT() asm volatile("cp.async.commit_group;" ::: "memory")
#define CP_WAIT0()  asm volatile("cp.async.wait_group 0;" ::: "memory")

__device__ __forceinline__ uint32_t pack_h2(__half a, __half b) {
    __half2 v(a, b);
    return *(uint32_t*)&v;
}

// ---------------------------------------------------------------------------
__global__ void prep_kernel(const float* __restrict__ x, int N, int rowsPad) {
    int w = (blockIdx.x * blockDim.x + threadIdx.x) >> 5;
    int lane = threadIdx.x & 31;
    if (w >= rowsPad) return;
    float4 v = make_float4(0.f, 0.f, 0.f, 0.f);
    if (w < N) {
        v = ((const float4*)(x + (size_t)w * D))[lane];
        float ss = v.x*v.x + v.y*v.y + v.z*v.z + v.w*v.w;
        #pragma unroll
        for (int o = 16; o > 0; o >>= 1) ss += __shfl_xor_sync(0xffffffffu, ss, o);
        float inv = 1.0f / (sqrtf(ss) + EPSn);
        v.x *= inv; v.y *= inv; v.z *= inv; v.w *= inv;
    }
    float f[4] = {v.x, v.y, v.z, v.w};
    __half h[4], lo[4];
    #pragma unroll
    for (int i = 0; i < 4; i++) {
        h[i]  = __float2half(f[i]);
        lo[i] = __float2half(f[i] - __half2float(h[i]));
    }
    uint2 uh, ul;
    uh.x = pack_h2(h[0], h[1]);  uh.y = pack_h2(h[2], h[3]);
    ul.x = pack_h2(lo[0], lo[1]); ul.y = pack_h2(lo[2], lo[3]);
    int t = w >> 7, rl = w & 127, d0 = lane * 4;
    uint32_t off = (uint32_t)rl * 256 + ((((d0 >> 3) ^ (rl & 7)) & 15) << 4) + ((d0 & 7) << 1);
    unsigned char* base = g_x + (size_t)t * 65536;
    *(uint2*)(base + off)         = uh;
    *(uint2*)(base + 32768 + off) = ul;
}

// ---------------------------------------------------------------------------
__global__ void zero_kernel() {
    int i = blockIdx.x * 512 + threadIdx.x;
    if (i < ITERS * K * D) g_mu_raw[K * D + i] = 0.0f;
    if (i < (ITERS + 1) * K) g_cc[i] = 0.0f;
}

__global__ void final_mu_kernel(float* __restrict__ mu_out) {
    int k = blockIdx.x, d = threadIdx.x;
    mu_out[k * D + d] = g_mu_raw[ITERS * K * D + k * D + d] / g_cc[ITERS * K + k];
}

// ---------------------------------------------------------------------------
template<bool LAST>
__global__ void __launch_bounds__(256, 1) iter_kernel(float* __restrict__ r_out,
                                                      const float* __restrict__ mu_init,
                                                      int N, int nT, int it) {
    extern __shared__ unsigned char sm[];
    int tid = threadIdx.x, w = tid >> 5, lane = tid & 31;
    int bid = blockIdx.x;
    int t0 = (int)((long long)bid * nT / gridDim.x);
    int t1 = (int)((long long)(bid + 1) * nT / gridDim.x);
    if (t0 >= t1) return;
    uint32_t sb = smem_u32(sm);
    uint32_t sMuH = sb + OFF_MU;
    uint32_t sR   = sb + OFF_R;

    // issue X(t0) load (64KB) first
    {
        const unsigned char* gx = g_x + (size_t)t0 * 65536;
        #pragma unroll
        for (int j = 0; j < 16; j++)
            cp16(sb + OFF_X + (tid + 256 * j) * 16, gx + (tid + 256 * j) * 16);
    }
    CP_COMMIT();

    // ---- fused mu update ----
    {
        int kk = tid & 63, dpart = tid >> 6;
        const float* msrc = (it == 0) ? mu_init : (g_mu_raw + (size_t)it * (K * D));
        float cinv = (it == 0) ? 1.0f : (1.0f / g_cc[it * K + kk]);
        const float* row = msrc + kk * D + dpart * 32;
        float v[32];
        float ss = 0.0f;
        #pragma unroll
        for (int j = 0; j < 32; j++) {
            float x = row[j] * cinv;
            v[j] = x;
            ss += x * x;
        }
        float* snorm = (float*)(sm + OFF_CNT);
        snorm[tid] = ss;
        __syncthreads();
        float tot = snorm[kk] + snorm[kk + 64] + snorm[kk + 128] + snorm[kk + 192];
        float inv = 1.0f / (sqrtf(tot) + EPSn);
        #pragma unroll
        for (int j = 0; j < 32; j += 2) {
            float n0 = v[j] * inv, n1 = v[j + 1] * inv;
            __half h0 = __float2half(n0), h1 = __float2half(n1);
            __half l0 = __float2half(n0 - __half2float(h0));
            __half l1 = __float2half(n1 - __half2float(h1));
            int d = dpart * 32 + j;
            uint32_t off = (uint32_t)kk * 256 + ((((d >> 3) ^ (kk & 7)) & 15) << 4) + ((d & 7) << 1);
            *(uint32_t*)(sm + OFF_MU + off)         = pack_h2(h0, h1);
            *(uint32_t*)(sm + OFF_MU + 16384 + off) = pack_h2(l0, l1);
        }
    }
    CP_WAIT0();
    __syncthreads();

    float C2[8][4];
    #pragma unroll
    for (int f = 0; f < 8; f++)
        #pragma unroll
        for (int q = 0; q < 4; q++) C2[f][q] = 0.0f;
    float cacc[8];
    #pragma unroll
    for (int j = 0; j < 8; j++) cacc[j] = 0.0f;

    // GEMM1 tiling: 32 rows x 32 kc per warp
    int rb  = w & 3, kcb = w >> 2;
    int R0  = rb * 32, KC0 = kcb * 32;
    // GEMM2 tiling: 32 kc x 32 d per warp
    int kc0m = (w & 1) * 32, d0 = (w >> 1) * 32;
    int g = lane >> 2, j2 = lane & 3;

    float* sSum = (float*)(sm + OFF_CNT);          // [2][128]
    float* scnt = (float*)(sm + OFF_CNT + 1024);   // [8][32]

    for (int t = t0; t < t1; t++) {
        int buf = (t - t0) & 1;
        uint32_t sX = sb + OFF_X + buf * 65536;       // Xh; Xl at +32768
        if (t + 1 < t1) {
            const unsigned char* gx = g_x + (size_t)(t + 1) * 65536;
            uint32_t dst = sb + OFF_X + (buf ^ 1) * 65536;
            #pragma unroll
            for (int j = 0; j < 16; j++)
                cp16(dst + (tid + 256 * j) * 16, gx + (tid + 256 * j) * 16);
        }
        CP_COMMIT();

        // ---- GEMM1: C1[32 rows x 32 kc] = X . Mu^T (3-term split) ----
        float C1[8][4];   // [mblk*4 + fp*2 + n8]
        #pragma unroll
        for (int f = 0; f < 8; f++)
            #pragma unroll
            for (int q = 0; q < 4; q++) C1[f][q] = 0.0f;
        #pragma unroll
        for (int ks = 0; ks < 8; ks++) {
            uint32_t ah[2][4], al[2][4], bh[2][4], bl[2][4];
            int ac = ks * 16 + ((lane >> 4) << 3);
            #pragma unroll
            for (int mb = 0; mb < 2; mb++) {
                int ar = R0 + mb * 16 + (lane & 15);
                uint32_t addr = sX + (uint32_t)ar * 256 + ((((ac >> 3) ^ (ar & 7)) & 15) << 4);
                ldsm_x4(ah[mb], addr);
                ldsm_x4(al[mb], addr + 32768);
            }
            int bc = ks * 16 + (((lane >> 3) & 1) << 3);
            #pragma unroll
            for (int fp = 0; fp < 2; fp++) {
                int brow = KC0 + fp * 16 + ((lane >> 4) << 3) + (lane & 7);
                uint32_t addr = sMuH + (uint32_t)brow * 256 + ((((bc >> 3) ^ (brow & 7)) & 15) << 4);
                ldsm_x4(bh[fp], addr);
                ldsm_x4(bl[fp], addr + 16384);
            }
            // term-major: hh, lh, hl (reuse distance 8)
            #pragma unroll
            for (int mb = 0; mb < 2; mb++)
                #pragma unroll
                for (int fp = 0; fp < 2; fp++) {
                    mma_f16(C1[mb*4+fp*2+0], ah[mb], bh[fp]);
                    mma_f16(C1[mb*4+fp*2+1], ah[mb], bh[fp] + 2);
                }
            #pragma unroll
            for (int mb = 0; mb < 2; mb++)
                #pragma unroll
                for (int fp = 0; fp < 2; fp++) {
                    mma_f16(C1[mb*4+fp*2+0], al[mb], bh[fp]);
                    mma_f16(C1[mb*4+fp*2+1], al[mb], bh[fp] + 2);
                }
            #pragma unroll
            for (int mb = 0; mb < 2; mb++)
                #pragma unroll
                for (int fp = 0; fp < 2; fp++) {
                    mma_f16(C1[mb*4+fp*2+0], ah[mb], bl[fp]);
                    mma_f16(C1[mb*4+fp*2+1], ah[mb], bl[fp] + 2);
                }
        }

        // ---- softmax: exp + cross-warp row sums (rows shared by 2 kc-warps) ----
        #pragma unroll
        for (int f = 0; f < 8; f++)
            #pragma unroll
            for (int q = 0; q < 4; q++) C1[f][q] = __expf(TEMP * C1[f][q]);
        #pragma unroll
        for (int mb = 0; mb < 2; mb++) {
            float sg = 0.0f, sg8 = 0.0f;
            #pragma unroll
            for (int ff = 0; ff < 4; ff++) {
                sg  += C1[mb*4+ff][0] + C1[mb*4+ff][1];
                sg8 += C1[mb*4+ff][2] + C1[mb*4+ff][3];
            }
            sg  += __shfl_xor_sync(0xffffffffu, sg, 1);
            sg  += __shfl_xor_sync(0xffffffffu, sg, 2);
            sg8 += __shfl_xor_sync(0xffffffffu, sg8, 1);
            sg8 += __shfl_xor_sync(0xffffffffu, sg8, 2);
            if (j2 == 0) {
                sSum[kcb * 128 + R0 + mb * 16 + g]     = sg;
                sSum[kcb * 128 + R0 + mb * 16 + g + 8] = sg8;
            }
        }
        __syncthreads();

        // ---- scale, write R to smem, counts ----
        #pragma unroll
        for (int mb = 0; mb < 2; mb++) {
            int row0 = R0 + mb * 16 + g, row1 = row0 + 8;
            int grow0 = t * TILE + row0, grow1 = t * TILE + row1;
            float inv0 = (grow0 < N) ? __fdividef(1.0f, sSum[row0] + sSum[128 + row0]) : 0.0f;
            float inv1 = (grow1 < N) ? __fdividef(1.0f, sSum[row1] + sSum[128 + row1]) : 0.0f;
            #pragma unroll
            for (int ff = 0; ff < 4; ff++) {
                int f = mb * 4 + ff;
                float r0a = C1[f][0] * inv0, r0b = C1[f][1] * inv0;
                float r1a = C1[f][2] * inv1, r1b = C1[f][3] * inv1;
                cacc[ff*2]   += r0a + r1a;
                cacc[ff*2+1] += r0b + r1b;
                int fg = kcb * 4 + ff;              // global n8 block
                int kc = 8 * fg + 2 * j2;
                {
                    uint32_t off = (uint32_t)row0 * 128 + (((fg ^ (row0 & 7)) & 7) << 4) + (j2 << 2);
                    *(uint32_t*)(sm + OFF_R + off) = pack_h2(__float2half(r0a), __float2half(r0b));
                }
                {
                    uint32_t off = (uint32_t)row1 * 128 + (((fg ^ (row1 & 7)) & 7) << 4) + (j2 << 2);
                    *(uint32_t*)(sm + OFF_R + off) = pack_h2(__float2half(r1a), __float2half(r1b));
                }
                if (LAST) {
                    if (grow0 < N) *(float2*)(r_out + (size_t)grow0 * K + kc) = make_float2(r0a, r0b);
                    if (grow1 < N) *(float2*)(r_out + (size_t)grow1 * K + kc) = make_float2(r1a, r1b);
                }
            }
        }
        __syncthreads();

        // ---- GEMM2: C2[32 kc x 32 d] += Rh^T . Xh (single term) ----
        #pragma unroll
        for (int ks = 0; ks < 8; ks++) {
            int row0k = ks * 16;
            uint32_t rA[2][4], bh[2][4];
            int arm = row0k + (lane & 7) + ((lane >> 4) << 3);
            #pragma unroll
            for (int mb = 0; mb < 2; mb++) {
                int acm = kc0m + mb * 16 + (((lane >> 3) & 1) << 3);
                uint32_t addr = sR + (uint32_t)arm * 128 + ((((acm >> 3) ^ (arm & 7)) & 7) << 4);
                ldsm_x4t(rA[mb], addr);
            }
            int brm = row0k + (((lane >> 3) & 1) << 3) + (lane & 7);
            #pragma unroll
            for (int fp = 0; fp < 2; fp++) {
                int d0c = d0 + fp * 16 + ((lane >> 4) << 3);
                uint32_t addr = sX + (uint32_t)brm * 256 + ((((d0c >> 3) ^ (brm & 7)) & 15) << 4);
                ldsm_x4t(bh[fp], addr);
            }
            #pragma unroll
            for (int mb = 0; mb < 2; mb++)
                #pragma unroll
                for (int fp = 0; fp < 2; fp++) {
                    mma_f16(C2[mb*4+fp*2+0], rA[mb], bh[fp]);
                    mma_f16(C2[mb*4+fp*2+1], rA[mb], bh[fp] + 2);
                }
        }
        CP_WAIT0();
        __syncthreads();
    }

    // ---- epilogue: counts (GEMM1 mapping: warp covers kc KC0..KC0+31) ----
    #pragma unroll
    for (int j = 0; j < 8; j++) {
        cacc[j] += __shfl_xor_sync(0xffffffffu, cacc[j], 4);
        cacc[j] += __shfl_xor_sync(0xffffffffu, cacc[j], 8);
        cacc[j] += __shfl_xor_sync(0xffffffffu, cacc[j], 16);
    }
    if (lane < 4) {
        #pragma unroll
        for (int ff = 0; ff < 4; ff++) {
            scnt[w * 32 + ff * 8 + 2 * lane]     = cacc[ff*2];
            scnt[w * 32 + ff * 8 + 2 * lane + 1] = cacc[ff*2+1];
        }
    }
    __syncthreads();
    if (tid < K) {
        int kcblk = tid >> 5, lc = tid & 31;
        float c = 0.0f;
        #pragma unroll
        for (int rbb = 0; rbb < 4; rbb++)
            c += scnt[(kcblk * 4 + rbb) * 32 + lc];
        atomicAdd(&g_cc[(it + 1) * K + tid], c);
    }
    // ---- epilogue: mean via atomics (GEMM2 mapping) ----
    float* gm = g_mu_raw + (size_t)(it + 1) * (K * D);
    #pragma unroll
    for (int mb = 0; mb < 2; mb++) {
        int krow0 = kc0m + mb * 16 + g, krow1 = krow0 + 8;
        #pragma unroll
        for (int ff = 0; ff < 4; ff++) {
            int f = mb * 4 + ff;
            int dd = d0 + (ff >> 1) * 16 + (ff & 1) * 8 + 2 * j2;
            atomicAdd(&gm[krow0 * D + dd],     C2[f][0]);
            atomicAdd(&gm[krow0 * D + dd + 1], C2[f][1]);
            atomicAdd(&gm[krow1 * D + dd],     C2[f][2]);
            atomicAdd(&gm[krow1 * D + dd + 1], C2[f][3]);
        }
    }
}

// ---------------------------------------------------------------------------
extern "C" void kernel_launch(void* const* d_in, const int* in_sizes, int n_in,
                              void* d_out, int out_size) {
    const float* embeds = (const float*)d_in[0];
    const float* init   = (const float*)d_in[1];
    int N = in_sizes[0] / D;
    int nT = (N + TILE - 1) / TILE;
    if (nT > NT_MAX) nT = NT_MAX;
    float* out_mu = (float*)d_out;
    float* out_r  = (float*)d_out + K * D;

    cudaFuncSetAttribute(iter_kernel<false>, cudaFuncAttributeMaxDynamicSharedMemorySize, SMEM_TOTAL);
    cudaFuncSetAttribute(iter_kernel<true>,  cudaFuncAttributeMaxDynamicSharedMemorySize, SMEM_TOTAL);

    int rowsPad = nT * TILE;
    prep_kernel<<<(rowsPad + 7) / 8, 256>>>(embeds, N, rowsPad);
    zero_kernel<<<(ITERS * K * D + 511) / 512, 512>>>();

    for (int it = 0; it < ITERS; it++) {
        if (it == ITERS - 1)
            iter_kernel<true><<<NB, 256, SMEM_TOTAL>>>(out_r, init, N, nT, it);
        else
            iter_kernel<false><<<NB, 256, SMEM_TOTAL>>>(nullptr, init, N, nT, it);
    }
    final_mu_kernel<<<K, 128>>>(out_mu);
}